// round 4
// baseline (speedup 1.0000x reference)
#include <cuda_runtime.h>
#include <cstdint>

// v, out: [8, 4096, 16, 64] f32 ; w: [1, 16, 127]
// offset(b,s,h,e) = ((b*4096 + s)*16 + h)*64 + e ; s = s1*64 + s2
#define SSTR   1024        // floats between consecutive s rows
#define NW     127

// Block = (b, h, e-quarter of 16 floats). Grid 512, 256 threads.
// Warps 0-3 (f-half): thread owns (s2, s2+32) x one float4 of e; loops s1.
// Warps 4-7 (u-half): thread owns (s1, s1+32); loops s2.
// No shuffles, no barriers in the hot loop; u-half's loads hit L2.
__global__ __launch_bounds__(256, 3)
void fftbias2d_v3(const float* __restrict__ v,
                  const float* __restrict__ wg,
                  float* __restrict__ out) {
    const int bid = blockIdx.x;
    const int eq  = bid & 3;                 // e-quarter
    const int h   = (bid >> 2) & 15;
    const int b   = bid >> 6;
    const int t   = threadIdx.x;

    __shared__ float  w_ext[128];
    __shared__ __align__(16) float4 f_sh [64][4];   // f[s2][ef]
    __shared__ __align__(16) float4 u_sh [64][4];   // u[s1][ef]
    __shared__ __align__(16) float4 rv_sh[64][4];   // RxV[j][ef]
    __shared__ __align__(16) float4 ru_sh[64][4];   // RxU[j][ef]

    // Extended filter: K[j][s] = w_ext[j + 64 - s], index in [1,127];
    // w_ext[127] aliases w[0] (127-circular convolution).
    if (t < NW)  w_ext[t]   = wg[h * NW + t];
    if (t == NW) w_ext[NW]  = wg[h * NW];

    const float* vb = v + ((size_t)b * 4096 * 16 + h) * 64 + eq * 16;

    const int tt = t & 127;
    const int ef = tt & 3;                   // float4 index within quarter
    const int sq = tt >> 2;                  // 0..31

    float4 aa = make_float4(0.f, 0.f, 0.f, 0.f);
    float4 ab = make_float4(0.f, 0.f, 0.f, 0.f);

    if (t < 128) {
        // ---- f-half: f[s2][e] = sum_s1 v[s1*64+s2][e] ----
        const float* pa = vb + (size_t)sq        * SSTR + ef * 4;
        const float* pb = vb + (size_t)(sq + 32) * SSTR + ef * 4;
        #pragma unroll 4
        for (int s1 = 0; s1 < 64; ++s1) {
            const size_t off = (size_t)s1 * 64 * SSTR;
            const float4 va = *(const float4*)(pa + off);
            const float4 vB = *(const float4*)(pb + off);
            aa.x += va.x; aa.y += va.y; aa.z += va.z; aa.w += va.w;
            ab.x += vB.x; ab.y += vB.y; ab.z += vB.z; ab.w += vB.w;
        }
        f_sh[sq     ][ef] = aa;
        f_sh[sq + 32][ef] = ab;
    } else {
        // ---- u-half: u[s1][e] = sum_s2 v[s1*64+s2][e] ----
        const float* pa = vb + (size_t)sq        * 64 * SSTR + ef * 4;
        const float* pb = vb + (size_t)(sq + 32) * 64 * SSTR + ef * 4;
        #pragma unroll 4
        for (int s2 = 0; s2 < 64; ++s2) {
            const size_t off = (size_t)s2 * SSTR;
            const float4 va = *(const float4*)(pa + off);
            const float4 vB = *(const float4*)(pb + off);
            aa.x += va.x; aa.y += va.y; aa.z += va.z; aa.w += va.w;
            ab.x += vB.x; ab.y += vB.y; ab.z += vB.z; ab.w += vB.w;
        }
        u_sh[sq     ][ef] = aa;
        u_sh[sq + 32][ef] = ab;
    }
    __syncthreads();

    // ---- Phase 2: RxV[j] = sum_s K[j,s] f[s] ; RxU[j] = sum_s K[j,s] u[s]
    {
        const int ef2 = t & 3;
        const int j   = t >> 2;              // 0..63
        float4 rv = make_float4(0.f, 0.f, 0.f, 0.f);
        float4 ru = make_float4(0.f, 0.f, 0.f, 0.f);
        #pragma unroll 4
        for (int s = 0; s < 64; ++s) {
            const float wsc = w_ext[j + 64 - s];
            const float4 fv = f_sh[s][ef2];
            const float4 uv = u_sh[s][ef2];
            rv.x += wsc * fv.x; rv.y += wsc * fv.y;
            rv.z += wsc * fv.z; rv.w += wsc * fv.w;
            ru.x += wsc * uv.x; ru.y += wsc * uv.y;
            ru.z += wsc * uv.z; ru.w += wsc * uv.w;
        }
        rv_sh[j][ef2] = rv;
        ru_sh[j][ef2] = ru;
    }
    __syncthreads();

    // ---- Phase 3: out[b, s1*64+s2, h, e] = RxV[s2][e] + RxU[s1][e] ----
    {
        const int ef3 = t & 3;
        const int s2  = t >> 2;              // 0..63
        const float4 rv4 = rv_sh[s2][ef3];
        float* ob = out + ((size_t)b * 4096 * 16 + h) * 64 + eq * 16
                        + ef3 * 4 + (size_t)s2 * SSTR;
        #pragma unroll 4
        for (int s1 = 0; s1 < 64; ++s1) {
            const float4 ru4 = ru_sh[s1][ef3];
            float4 o;
            o.x = rv4.x + ru4.x;
            o.y = rv4.y + ru4.y;
            o.z = rv4.z + ru4.z;
            o.w = rv4.w + ru4.w;
            *(float4*)(ob + (size_t)s1 * 64 * SSTR) = o;
        }
    }
}

extern "C" void kernel_launch(void* const* d_in, const int* in_sizes, int n_in,
                              void* d_out, int out_size) {
    (void)in_sizes; (void)n_in; (void)out_size;
    const float* v = (const float*)d_in[0];
    const float* w = (const float*)d_in[1];
    float* o = (float*)d_out;
    fftbias2d_v3<<<512, 256>>>(v, w, o);
}

// round 5
// speedup vs baseline: 1.5230x; 1.5230x over previous
#include <cuda_runtime.h>
#include <cstdint>

// v, out: [8, 4096, 16, 64] f32 ; w: [1, 16, 127]
// offset(b,s,h,e) = ((b*4096 + s)*16 + h)*64 + e ; s = s1*64 + s2
#define SSTR 1024     // floats between consecutive s rows
#define NW   127

// Block = (b, h, e-half). Grid 256, 256 threads (8 warps).
// Warp-lane geometry everywhere: so = l>>3 (s-row offset), e4 = l&7 (float4 in
// e-half) -> every LDG.128/STG.128 covers 4 consecutive s-rows x 128B = 4 full
// cache lines.
__global__ __launch_bounds__(256, 4)
void fftbias2d_v4(const float* __restrict__ v,
                  const float* __restrict__ wg,
                  float* __restrict__ out) {
    const int bid = blockIdx.x;
    const int eh  = bid & 1;                 // e-half (32 floats)
    const int h   = (bid >> 1) & 15;
    const int b   = bid >> 5;

    const int t  = threadIdx.x;
    const int w  = t >> 5;                   // warp 0..7
    const int l  = t & 31;
    const int so = l >> 3;                   // 0..3
    const int e4 = l & 7;                    // 0..7

    __shared__ float w_ext[128];
    __shared__ __align__(16) float4 f_sh [64][8];   // f[s2][e4]
    __shared__ __align__(16) float4 u_sh [64][8];   // u[s1][e4]
    __shared__ __align__(16) float4 rv_sh[64][8];   // RxV[j][e4]
    __shared__ __align__(16) float4 ru_sh[64][8];   // RxU[j][e4]

    // K[j][s] = w_ext[j + 64 - s], index in [1,127]; w_ext[127] aliases w[0].
    if (t < NW)  w_ext[t]  = wg[h * NW + t];
    if (t == NW) w_ext[NW] = wg[h * NW];

    const float* vb = v + (size_t)b * 4096 * SSTR + h * 64 + eh * 32 + e4 * 4;

    // ---------------- Phase 1: tile loop over s1 groups of 8 ----------------
    // f: warp owns s2 quads {w, w+8} (s2 = 4w+so, 4w+32+so), reg accumulators.
    // u: warp owns s1 = 8*tile + w, loops 16 s2 quads, shuffle-reduce over so.
    float4 f0 = make_float4(0.f, 0.f, 0.f, 0.f);
    float4 f1 = make_float4(0.f, 0.f, 0.f, 0.f);
    const int s2a = 4 * w + so;

    for (int tile = 0; tile < 8; ++tile) {
        const int s1b = tile * 8;
        // f-pass over this tile's 8 s1 rows
        #pragma unroll
        for (int i = 0; i < 8; ++i) {
            const float* r = vb + (size_t)((s1b + i) * 64) * SSTR;
            const float4 a = *(const float4*)(r + (size_t)s2a * SSTR);
            const float4 c = *(const float4*)(r + (size_t)(s2a + 32) * SSTR);
            f0.x += a.x; f0.y += a.y; f0.z += a.z; f0.w += a.w;
            f1.x += c.x; f1.y += c.y; f1.z += c.z; f1.w += c.w;
        }
        // u-pass: s1 = s1b + w, all 64 s2 (16 quads) — tile is L1-hot now
        {
            const float* r = vb + (size_t)((s1b + w) * 64 + so) * SSTR;
            float4 ua = make_float4(0.f, 0.f, 0.f, 0.f);
            #pragma unroll
            for (int q = 0; q < 16; ++q) {
                const float4 a = *(const float4*)(r + (size_t)(4 * q) * SSTR);
                ua.x += a.x; ua.y += a.y; ua.z += a.z; ua.w += a.w;
            }
            ua.x += __shfl_xor_sync(0xffffffffu, ua.x, 8);
            ua.y += __shfl_xor_sync(0xffffffffu, ua.y, 8);
            ua.z += __shfl_xor_sync(0xffffffffu, ua.z, 8);
            ua.w += __shfl_xor_sync(0xffffffffu, ua.w, 8);
            ua.x += __shfl_xor_sync(0xffffffffu, ua.x, 16);
            ua.y += __shfl_xor_sync(0xffffffffu, ua.y, 16);
            ua.z += __shfl_xor_sync(0xffffffffu, ua.z, 16);
            ua.w += __shfl_xor_sync(0xffffffffu, ua.w, 16);
            if (l < 8) u_sh[s1b + w][l] = ua;
        }
    }
    f_sh[s2a     ][e4] = f0;
    f_sh[s2a + 32][e4] = f1;
    __syncthreads();

    // ---------------- Phase 2: RxV[j] = sum_s K[j,s] f[s]; same for u ------
    // warp = one e4 slice (broadcast LDS); lane = j, handles j and j+32.
    {
        float4 rv0 = make_float4(0.f,0.f,0.f,0.f), rv1 = rv0;
        float4 ru0 = rv0, ru1 = rv0;
        #pragma unroll 4
        for (int s = 0; s < 64; ++s) {
            const float4 fv = f_sh[s][w];           // broadcast
            const float4 uv = u_sh[s][w];           // broadcast
            const float wa = w_ext[l + 64 - s];     // j = l
            const float wb = w_ext[l + 96 - s];     // j = l + 32
            rv0.x += wa * fv.x; rv0.y += wa * fv.y; rv0.z += wa * fv.z; rv0.w += wa * fv.w;
            rv1.x += wb * fv.x; rv1.y += wb * fv.y; rv1.z += wb * fv.z; rv1.w += wb * fv.w;
            ru0.x += wa * uv.x; ru0.y += wa * uv.y; ru0.z += wa * uv.z; ru0.w += wa * uv.w;
            ru1.x += wb * uv.x; ru1.y += wb * uv.y; ru1.z += wb * uv.z; ru1.w += wb * uv.w;
        }
        rv_sh[l     ][w] = rv0;
        rv_sh[l + 32][w] = rv1;
        ru_sh[l     ][w] = ru0;
        ru_sh[l + 32][w] = ru1;
    }
    __syncthreads();

    // ---------------- Phase 3: out[s1*64+s2] = RxV[s2] + RxU[s1] -----------
    // Same 4-line-per-store geometry: warp stores s2 quads {w, w+8}.
    {
        const float4 rva = rv_sh[s2a     ][e4];
        const float4 rvb = rv_sh[s2a + 32][e4];
        float* ob = out + (size_t)b * 4096 * SSTR + h * 64 + eh * 32 + e4 * 4;
        #pragma unroll 4
        for (int s1 = 0; s1 < 64; ++s1) {
            const float4 ru = ru_sh[s1][e4];        // broadcast
            float* r = ob + (size_t)(s1 * 64) * SSTR;
            float4 o0, o1;
            o0.x = rva.x + ru.x; o0.y = rva.y + ru.y;
            o0.z = rva.z + ru.z; o0.w = rva.w + ru.w;
            o1.x = rvb.x + ru.x; o1.y = rvb.y + ru.y;
            o1.z = rvb.z + ru.z; o1.w = rvb.w + ru.w;
            *(float4*)(r + (size_t)s2a * SSTR)        = o0;
            *(float4*)(r + (size_t)(s2a + 32) * SSTR) = o1;
        }
    }
}

extern "C" void kernel_launch(void* const* d_in, const int* in_sizes, int n_in,
                              void* d_out, int out_size) {
    (void)in_sizes; (void)n_in; (void)out_size;
    const float* v = (const float*)d_in[0];
    const float* w = (const float*)d_in[1];
    float* o = (float*)d_out;
    fftbias2d_v4<<<256, 256>>>(v, w, o);
}